// round 7
// baseline (speedup 1.0000x reference)
#include <cuda_runtime.h>
#include <math.h>

#define Bsz 128
#define Tsz 256
#define Lw  4
#define DCc 128
#define DWw 128
#define Hh  256
#define Vv  6000
#define NEGV -1e30f

// ---------------- device global scratch (no allocations allowed) ----------------
__device__ float g_proj[Vv * Lw * DCc];                 // PROJ[ch][w][e]  (12.3 MB)
__device__ float g_word[(size_t)Tsz * Bsz * Lw * DWw];  // word[t][b][w][e] (64 MB)
__device__ float g_su[Tsz * Bsz * Lw];                  // su[t][b][w]
__device__ float g_rh[8 * Bsz * Hh];                    // h ring   [slot][b][u]
__device__ float g_rc[8 * Bsz * Hh];                    // c ring
__device__ float g_rp[8 * Bsz * DWw];                   // pred ring [slot][b][e]
__device__ int   g_best_i[Bsz];
__device__ unsigned g_arrive;

__device__ __forceinline__ float sigm(float x) { return 1.0f / (1.0f + expf(-x)); }

// ---------------- grid barrier (monotonic epoch; reset by k_init) ----------------
__device__ __forceinline__ void gbar(unsigned target) {
    __syncthreads();
    if (threadIdx.x == 0) {
        __threadfence();
        atomicAdd(&g_arrive, 1u);
        volatile unsigned* p = &g_arrive;
        while (*p < target) { }
        __threadfence();
    }
    __syncthreads();
}

// ---------------- PROJ table: proj = tanh((sigmoid(emb@rW[w]+rb[w])*emb)@cW + cb) ----
__global__ void k_proj(const float* __restrict__ emb,
                       const float* __restrict__ rW,
                       const float* __restrict__ rb,
                       const float* __restrict__ cW,
                       const float* __restrict__ cb) {
    extern __shared__ float sm[];
    float* srW = sm;                // 16384
    float* scW = srW + 16384;       // 16384
    float* srb = scW + 16384;       // 128
    float* scb = srb + 128;         // 128
    float* se  = scb + 128;         // 128
    float* sh  = se + 128;          // 128
    const int tid = threadIdx.x;    // 128 threads
    const int w = blockIdx.y;
    const int c0 = blockIdx.x * 64;

    for (int i = tid; i < 16384; i += 128) {
        srW[i] = rW[w * 16384 + i];
        scW[i] = cW[i];
    }
    srb[tid] = rb[w * 128 + tid];
    scb[tid] = cb[tid];
    __syncthreads();

    const int cend = (c0 + 64 < Vv) ? c0 + 64 : Vv;
    for (int ch = c0; ch < cend; ch++) {
        se[tid] = emb[ch * 128 + tid];
        __syncthreads();
        float g = srb[tid];
        #pragma unroll 8
        for (int d = 0; d < 128; d++) g = fmaf(se[d], srW[d * 128 + tid], g);
        sh[tid] = sigm(g) * se[tid];
        __syncthreads();
        float p = scb[tid];
        #pragma unroll 8
        for (int d = 0; d < 128; d++) p = fmaf(sh[d], scW[d * 128 + tid], p);
        g_proj[(ch * Lw + w) * DCc + tid] = tanhf(p);
        __syncthreads();
    }
}

// ---------------- word[t][b][w][:] = mean of PROJ rows; su = U . word --------------
__global__ void k_word(const int* __restrict__ chars, const float* __restrict__ U) {
    const int t = blockIdx.x, b = blockIdx.y, tid = threadIdx.x; // 128 threads
    const int lane = tid & 31, wid = tid >> 5;
    __shared__ int ch[4];
    __shared__ float red[4];
    if (tid < 4) {
        int ti = t - tid;
        ch[tid] = (ti >= 0) ? chars[b * Tsz + ti] : 0;
    }
    __syncthreads();
    const float inv[4] = {1.0f, 0.5f, 1.0f / 3.0f, 0.25f};
    const float uw = U[tid];
    #pragma unroll
    for (int w = 0; w < 4; w++) {
        float acc = 0.0f;
        for (int c = 0; c <= w; c++) acc += g_proj[(ch[c] * Lw + w) * DCc + tid];
        acc *= inv[w];
        g_word[(((size_t)t * Bsz + b) * Lw + w) * DWw + tid] = acc;
        float v = acc * uw;
        #pragma unroll
        for (int o = 16; o; o >>= 1) v += __shfl_xor_sync(0xffffffffu, v, o);
        if (lane == 0) red[wid] = v;
        __syncthreads();
        if (tid == 0) g_su[(t * Bsz + b) * Lw + w] = red[0] + red[1] + red[2] + red[3];
        __syncthreads();
    }
}

// ---------------- init: c1,h1,pred0; prefill rings slots 4..7; reset barrier --------
__global__ void k_init(const float* __restrict__ lk, const float* __restrict__ lb,
                       const float* __restrict__ pW, const float* __restrict__ pb,
                       const float* __restrict__ bos) {
    __shared__ float sh1[256], sc1[256], sp0[128];
    const int u = threadIdx.x;  // 256 threads
    const int b = blockIdx.x;
    float zi = lb[u], zj = lb[256 + u], zf = lb[512 + u], zo = lb[768 + u];
    (void)zf;
    for (int d = 0; d < 128; d++) {
        float x = bos[d];
        const float* row = lk + d * 1024;
        zi = fmaf(x, row[u], zi);
        zj = fmaf(x, row[256 + u], zj);
        zo = fmaf(x, row[768 + u], zo);
    }
    float nc = sigm(zi) * tanhf(zj);      // c0 = 0
    float nh = tanhf(nc) * sigm(zo);
    sc1[u] = nc; sh1[u] = nh;
    __syncthreads();
    if (u < 128) {
        float p = pb[u];
        for (int q = 0; q < 256; q++) p = fmaf(sh1[q], pW[q * 128 + u], p);
        sp0[u] = tanhf(p);
    }
    __syncthreads();
    for (int s = 4; s < 8; s++) {
        g_rc[(s * Bsz + b) * Hh + u] = sc1[u];
        g_rh[(s * Bsz + b) * Hh + u] = sh1[u];
        if (u < 128) g_rp[(s * Bsz + b) * DWw + u] = sp0[u];
    }
    if (b == 0 && u == 0) g_arrive = 0u;
}

// ---------------- persistent sequential kernel ----------------
// P1: CTA = batch row b.   P2: CTA = (bg = b>>4 : 16 rows, ug = b&15 : 16 units x 4 gates)
__global__ void __launch_bounds__(256, 1) k_run(
    const float* __restrict__ lk, const float* __restrict__ lb,
    const float* __restrict__ pW, const float* __restrict__ pb,
    float* __restrict__ out) {
    extern __shared__ float sm[];
    float* spw   = sm;              // 32768: pred_W [u][e]
    float* swl   = spw + 32768;     // 24576: Wl[k][uu*4+g]
    float* sxh   = swl + 24576;     // 256
    float* spred = sxh + 256;       // 128
    float* sbias = spred + 128;     // 64
    float* ssc   = sbias + 64;      // 8

    const int tid = threadIdx.x;
    const int b = blockIdx.x;
    const int bg = b >> 4, ug = b & 15;
    const int lane = tid & 31, wid = tid >> 5;
    const int r = tid >> 4, uu = tid & 15;       // P2 roles
    const int bb = bg * 16 + r;
    const int unit = ug * 16 + uu;

    for (int i = tid; i < 32768; i += 256) spw[i] = pW[i];
    for (int i = tid; i < 24576; i += 256) {
        int k = i >> 6, m = i & 63, u2 = m >> 2, g = m & 3;
        swl[i] = lk[k * 1024 + g * 256 + ug * 16 + u2];
    }
    if (tid < 64) { int u2 = tid >> 2, g = tid & 3; sbias[tid] = lb[g * 256 + ug * 16 + u2]; }
    float rpb = (tid < 128) ? pb[tid] : 0.0f;
    __syncthreads();

    unsigned nbar = 0;
    float* out_sc = out;
    float* out_wl = out + Bsz * Tsz;

    for (int t = 0; t < Tsz; t++) {
        // ================= P1 =================
        const int slot1 = (t + 7) & 7;  // (t-1) mod 8
        sxh[tid] = __ldcg(&g_rh[(slot1 * Bsz + b) * Hh + tid]);
        __syncthreads();
        if (tid < 128) {
            float p = rpb;
            #pragma unroll 8
            for (int q = 0; q < 256; q++) p = fmaf(sxh[q], spw[q * 128 + tid], p);
            p = tanhf(p);
            spred[tid] = p;
            g_rp[(slot1 * Bsz + b) * DWw + tid] = p;   // own-CTA data
        }
        __syncthreads();
        if (wid < 4) {
            float s;
            if (wid <= t) {
                const float* wp = &g_word[(((size_t)t * Bsz + b) * Lw + wid) * DWw];
                float acc = 0.0f;
                if (wid == 0) {
                    for (int e = lane; e < 128; e += 32) acc = fmaf(spred[e], wp[e], acc);
                } else {
                    const float* pp = &g_rp[(((t - 1 - wid) & 7) * Bsz + b) * DWw];
                    for (int e = lane; e < 128; e += 32) acc = fmaf(pp[e], wp[e], acc);
                }
                #pragma unroll
                for (int o = 16; o; o >>= 1) acc += __shfl_xor_sync(0xffffffffu, acc, o);
                s = acc + g_su[(t * Bsz + b) * Lw + wid];
            } else s = NEGV;
            if (lane == 0) ssc[wid] = s;
        }
        __syncthreads();
        if (tid == 0) {
            int best = 0; float bs = ssc[0];
            #pragma unroll
            for (int w = 1; w < 4; w++) if (ssc[w] > bs) { bs = ssc[w]; best = w; }
            __stcg(&g_best_i[b], best);
            out_sc[b * Tsz + t] = bs;
            out_wl[b * Tsz + t] = (float)(best + 1);
        }
        nbar++; gbar(nbar * 128u);

        // ================= P2 =================
        {
            const int best = __ldcg(&g_best_i[bb]);
            const int hs = (t - 1 - best) & 7;
            float zi = sbias[uu * 4 + 0], zj = sbias[uu * 4 + 1];
            float zf = sbias[uu * 4 + 2], zo = sbias[uu * 4 + 3];
            const float4* xw = (const float4*)&g_word[(((size_t)t * Bsz + bb) * Lw + best) * DWw];
            #pragma unroll 4
            for (int kq = 0; kq < 32; kq++) {
                float4 x4 = __ldcg(xw + kq);
                const float* w0 = &swl[(kq * 4) * 64 + uu * 4];
                float4 a = *(const float4*)(w0);
                float4 c = *(const float4*)(w0 + 64);
                float4 d = *(const float4*)(w0 + 128);
                float4 e = *(const float4*)(w0 + 192);
                zi = fmaf(x4.x, a.x, zi); zj = fmaf(x4.x, a.y, zj); zf = fmaf(x4.x, a.z, zf); zo = fmaf(x4.x, a.w, zo);
                zi = fmaf(x4.y, c.x, zi); zj = fmaf(x4.y, c.y, zj); zf = fmaf(x4.y, c.z, zf); zo = fmaf(x4.y, c.w, zo);
                zi = fmaf(x4.z, d.x, zi); zj = fmaf(x4.z, d.y, zj); zf = fmaf(x4.z, d.z, zf); zo = fmaf(x4.z, d.w, zo);
                zi = fmaf(x4.w, e.x, zi); zj = fmaf(x4.w, e.y, zj); zf = fmaf(x4.w, e.z, zf); zo = fmaf(x4.w, e.w, zo);
            }
            const float4* hw = (const float4*)&g_rh[(hs * Bsz + bb) * Hh];
            #pragma unroll 4
            for (int kq = 0; kq < 64; kq++) {
                float4 x4 = __ldcg(hw + kq);
                const float* w0 = &swl[(128 + kq * 4) * 64 + uu * 4];
                float4 a = *(const float4*)(w0);
                float4 c = *(const float4*)(w0 + 64);
                float4 d = *(const float4*)(w0 + 128);
                float4 e = *(const float4*)(w0 + 192);
                zi = fmaf(x4.x, a.x, zi); zj = fmaf(x4.x, a.y, zj); zf = fmaf(x4.x, a.z, zf); zo = fmaf(x4.x, a.w, zo);
                zi = fmaf(x4.y, c.x, zi); zj = fmaf(x4.y, c.y, zj); zf = fmaf(x4.y, c.z, zf); zo = fmaf(x4.y, c.w, zo);
                zi = fmaf(x4.z, d.x, zi); zj = fmaf(x4.z, d.y, zj); zf = fmaf(x4.z, d.z, zf); zo = fmaf(x4.z, d.w, zo);
                zi = fmaf(x4.w, e.x, zi); zj = fmaf(x4.w, e.y, zj); zf = fmaf(x4.w, e.z, zf); zo = fmaf(x4.w, e.w, zo);
            }
            float cp = __ldcg(&g_rc[(hs * Bsz + bb) * Hh + unit]);
            float nc = cp * sigm(zf) + sigm(zi) * tanhf(zj);
            float nh = tanhf(nc) * sigm(zo);
            const int ws = t & 7;
            __stcg(&g_rc[(ws * Bsz + bb) * Hh + unit], nc);
            __stcg(&g_rh[(ws * Bsz + bb) * Hh + unit], nh);
        }
        nbar++; gbar(nbar * 128u);
    }
}

// ---------------- launch ----------------
static const int PROJ_SMEM = (16384 + 16384 + 128 + 128 + 128 + 128) * 4;
static const int RUN_SMEM  = (32768 + 24576 + 256 + 128 + 64 + 8) * 4;

extern "C" void kernel_launch(void* const* d_in, const int* in_sizes, int n_in,
                              void* d_out, int out_size) {
    const int*   chars = (const int*)d_in[0];
    const float* emb   = (const float*)d_in[1];
    const float* rW    = (const float*)d_in[2];
    const float* rb    = (const float*)d_in[3];
    const float* cW    = (const float*)d_in[4];
    const float* cb    = (const float*)d_in[5];
    const float* lk    = (const float*)d_in[6];
    const float* lb    = (const float*)d_in[7];
    const float* pW    = (const float*)d_in[8];
    const float* pb    = (const float*)d_in[9];
    const float* U     = (const float*)d_in[10];
    const float* bos   = (const float*)d_in[11];

    cudaFuncSetAttribute(k_proj, cudaFuncAttributeMaxDynamicSharedMemorySize, PROJ_SMEM);
    cudaFuncSetAttribute(k_run,  cudaFuncAttributeMaxDynamicSharedMemorySize, RUN_SMEM);

    k_init<<<Bsz, 256>>>(lk, lb, pW, pb, bos);
    k_proj<<<dim3(94, Lw), 128, PROJ_SMEM>>>(emb, rW, rb, cW, cb);
    k_word<<<dim3(Tsz, Bsz), 128>>>(chars, U);
    k_run<<<Bsz, 256, RUN_SMEM>>>(lk, lb, pW, pb, (float*)d_out);
}

// round 9
// speedup vs baseline: 1.1864x; 1.1864x over previous
#include <cuda_runtime.h>
#include <math.h>

#define Bsz 128
#define Tsz 256
#define Lw  4
#define DCc 128
#define DWw 128
#define Hh  256
#define Vv  6000
#define NEGV -1e30f

typedef unsigned long long u64t;

// ---------------- device global scratch (no allocations allowed) ----------------
__device__ float g_proj[Vv * Lw * DCc];                 // PROJ[ch][w][e]
__device__ float g_word[(size_t)Tsz * Bsz * Lw * DWw];  // word[t][b][w][e]
__device__ float g_su[Tsz * Bsz * Lw];                  // su[t][b][w]
__device__ float g_rh[8 * Bsz * Hh];                    // h ring [slot][b][u]
__device__ float g_rc[8 * Bsz * Hh];                    // c ring
__device__ float g_rp[8 * Bsz * DWw];                   // pred ring [slot][b][e]
__device__ int   g_best_i[Bsz];
__device__ unsigned g_arr[8 * 32];                      // per-group barrier counters (padded)

__device__ __forceinline__ float sigm(float x) { return 1.0f / (1.0f + expf(-x)); }

// ---------------- packed f32x2 helpers ----------------
__device__ __forceinline__ u64t fma2(u64t a, u64t b, u64t c) {
    u64t d; asm("fma.rn.f32x2 %0, %1, %2, %3;" : "=l"(d) : "l"(a), "l"(b), "l"(c)); return d;
}
__device__ __forceinline__ u64t add2(u64t a, u64t b) {
    u64t d; asm("add.rn.f32x2 %0, %1, %2;" : "=l"(d) : "l"(a), "l"(b)); return d;
}
__device__ __forceinline__ u64t dup2(float x) {
    u64t r; asm("mov.b64 %0, {%1, %1};" : "=l"(r) : "f"(x)); return r;
}
__device__ __forceinline__ u64t pk2(float lo, float hi) {
    u64t r; asm("mov.b64 %0, {%1, %2};" : "=l"(r) : "f"(lo), "f"(hi)); return r;
}
__device__ __forceinline__ float2 unpk(u64t v) {
    float2 r; asm("mov.b64 {%0, %1}, %2;" : "=f"(r.x), "=f"(r.y) : "l"(v)); return r;
}

// ---------------- 16-CTA group barrier (monotonic epoch; reset by k_init) ----------
__device__ __forceinline__ void gbar(unsigned* ctr, unsigned target) {
    __syncthreads();
    if (threadIdx.x == 0) {
        __threadfence();
        atomicAdd(ctr, 1u);
        volatile unsigned* p = ctr;
        while (*p < target) { }
        __threadfence();
    }
    __syncthreads();
}

// ---------------- PROJ table (148 blocks = 1 wave, 2 chars/iter, 4 accumulators) ----
__global__ void k_proj(const float* __restrict__ emb,
                       const float* __restrict__ rW,
                       const float* __restrict__ rb,
                       const float* __restrict__ cW,
                       const float* __restrict__ cb) {
    extern __shared__ float sm[];
    float* srW = sm;               // 16384
    float* scW = srW + 16384;      // 16384
    float* srb = scW + 16384;      // 128
    float* scb = srb + 128;        // 128
    float* se  = scb + 128;        // 256
    float* sh  = se + 256;         // 256
    const int tid = threadIdx.x;   // 256 threads
    const int e = tid & 127, half = tid >> 7;
    const int w = blockIdx.y;

    for (int i = tid; i < 16384; i += 256) {
        srW[i] = rW[w * 16384 + i];
        scW[i] = cW[i];
    }
    if (tid < 128) { srb[tid] = rb[w * 128 + tid]; scb[tid] = cb[tid]; }
    __syncthreads();

    const int base = blockIdx.x * 163;
    for (int ci = 0; ci < 82; ci++) {
        const int ch = base + ci * 2 + half;
        const bool ok = (ci * 2 + half < 163) && (ch < Vv);
        se[half * 128 + e] = ok ? emb[ch * 128 + e] : 0.0f;
        __syncthreads();
        const float* seh = se + half * 128;
        float a0 = srb[e], a1 = 0.f, a2 = 0.f, a3 = 0.f;
        #pragma unroll 8
        for (int d = 0; d < 128; d += 4) {
            a0 = fmaf(seh[d + 0], srW[(d + 0) * 128 + e], a0);
            a1 = fmaf(seh[d + 1], srW[(d + 1) * 128 + e], a1);
            a2 = fmaf(seh[d + 2], srW[(d + 2) * 128 + e], a2);
            a3 = fmaf(seh[d + 3], srW[(d + 3) * 128 + e], a3);
        }
        float g = (a0 + a1) + (a2 + a3);
        sh[half * 128 + e] = sigm(g) * seh[e];
        __syncthreads();
        const float* shh = sh + half * 128;
        float p0 = scb[e], p1 = 0.f, p2 = 0.f, p3 = 0.f;
        #pragma unroll 8
        for (int d = 0; d < 128; d += 4) {
            p0 = fmaf(shh[d + 0], scW[(d + 0) * 128 + e], p0);
            p1 = fmaf(shh[d + 1], scW[(d + 1) * 128 + e], p1);
            p2 = fmaf(shh[d + 2], scW[(d + 2) * 128 + e], p2);
            p3 = fmaf(shh[d + 3], scW[(d + 3) * 128 + e], p3);
        }
        float p = (p0 + p1) + (p2 + p3);
        if (ok) g_proj[(ch * Lw + w) * DCc + e] = tanhf(p);
        __syncthreads();
    }
}

// ---------------- word + su tables ----------------
__global__ void k_word(const int* __restrict__ chars, const float* __restrict__ U) {
    const int t = blockIdx.x, b = blockIdx.y, tid = threadIdx.x; // 128 threads
    const int lane = tid & 31, wid = tid >> 5;
    __shared__ int ch[4];
    __shared__ float red[4];
    if (tid < 4) {
        int ti = t - tid;
        ch[tid] = (ti >= 0) ? chars[b * Tsz + ti] : 0;
    }
    __syncthreads();
    const float inv[4] = {1.0f, 0.5f, 1.0f / 3.0f, 0.25f};
    const float uw = U[tid];
    #pragma unroll
    for (int w = 0; w < 4; w++) {
        float acc = 0.0f;
        for (int c = 0; c <= w; c++) acc += g_proj[(ch[c] * Lw + w) * DCc + tid];
        acc *= inv[w];
        g_word[(((size_t)t * Bsz + b) * Lw + w) * DWw + tid] = acc;
        float v = acc * uw;
        #pragma unroll
        for (int o = 16; o; o >>= 1) v += __shfl_xor_sync(0xffffffffu, v, o);
        if (lane == 0) red[wid] = v;
        __syncthreads();
        if (tid == 0) g_su[(t * Bsz + b) * Lw + w] = red[0] + red[1] + red[2] + red[3];
        __syncthreads();
    }
}

// ---------------- init: c1,h1,pred0; prefill rings slots 4..7; reset barriers -------
__global__ void k_init(const float* __restrict__ lk, const float* __restrict__ lb,
                       const float* __restrict__ pW, const float* __restrict__ pb,
                       const float* __restrict__ bos) {
    __shared__ float sh1[256], sc1[256], sp0[128];
    const int u = threadIdx.x;  // 256 threads
    const int b = blockIdx.x;
    float zi = lb[u], zj = lb[256 + u], zo = lb[768 + u];
    for (int d = 0; d < 128; d++) {
        float x = bos[d];
        const float* row = lk + d * 1024;
        zi = fmaf(x, row[u], zi);
        zj = fmaf(x, row[256 + u], zj);
        zo = fmaf(x, row[768 + u], zo);
    }
    float nc = sigm(zi) * tanhf(zj);      // c0 = 0
    float nh = tanhf(nc) * sigm(zo);
    sc1[u] = nc; sh1[u] = nh;
    __syncthreads();
    if (u < 128) {
        float p = pb[u];
        for (int q = 0; q < 256; q++) p = fmaf(sh1[q], pW[q * 128 + u], p);
        sp0[u] = tanhf(p);
    }
    __syncthreads();
    for (int s = 4; s < 8; s++) {
        g_rc[(s * Bsz + b) * Hh + u] = sc1[u];
        g_rh[(s * Bsz + b) * Hh + u] = sh1[u];
        if (u < 128) g_rp[(s * Bsz + b) * DWw + u] = sp0[u];
    }
    if (b == 0 && u < 8) g_arr[u * 32] = 0u;
}

// ---------------- persistent sequential kernel ----------------
// CTA b: P1 (pred/score/argmax) for row b; P2 (LSTM) for rows bg*16..+15 x units
// ug*16..+15 (bg=b>>4, ug=b&15). P2 warp layout: 4 rows x 8 units.
// Sync: two 16-CTA group barriers per step (all cross-CTA deps are intra-group).
__global__ void __launch_bounds__(256, 1) k_run(
    const float* __restrict__ lk, const float* __restrict__ lb,
    const float* __restrict__ pW, const float* __restrict__ pb,
    float* __restrict__ out) {
    extern __shared__ float sm[];
    float* spw   = sm;              // 32768: pred_W [u][e]
    float* swl   = spw + 32768;     // 24576: Wl[k][lu*4+g]
    float* sxh   = swl + 24576;     // 256
    float* spred = sxh + 256;       // 128
    float* sred  = spred + 128;     // 256
    float* sbias = sred + 256;      // 64
    float* ssc   = sbias + 64;      // 8

    const int tid = threadIdx.x;
    const int b = blockIdx.x;
    const int bg = b >> 4, ug = b & 15;
    const int warp = tid >> 5, lane = tid & 31;
    const int rt = warp >> 1;                      // row tile 0..3
    const int lrow = rt * 4 + (lane >> 3);         // 0..15
    const int lunit = (warp & 1) * 8 + (lane & 7); // 0..15
    const int myrow = bg * 16 + lrow;
    const int unit  = ug * 16 + lunit;
    const int e1 = tid & 127, hf = tid >> 7;

    // ---- prologue: weights into smem ----
    for (int i = tid; i < 32768; i += 256) spw[i] = pW[i];
    for (int i = tid; i < 24576; i += 256) {
        int k = i >> 6, m = i & 63, u2 = m >> 2, g = m & 3;
        swl[i] = lk[k * 1024 + g * 256 + ug * 16 + u2];
    }
    if (tid < 64) { int u2 = tid >> 2, g = tid & 3; sbias[tid] = lb[g * 256 + ug * 16 + u2]; }
    const float rpb = (tid < 128) ? pb[tid] : 0.0f;
    __syncthreads();

    unsigned nbar = 0;
    float* out_sc = out;
    float* out_wl = out + Bsz * Tsz;
    unsigned* bar = &g_arr[bg * 32];

    for (int t = 0; t < Tsz; t++) {
        // ================= P1: pred + score + argmax (row b) =================
        const int slot1 = (t + 7) & 7;  // (t-1) mod 8
        sxh[tid] = __ldcg(&g_rh[(slot1 * Bsz + b) * Hh + tid]);
        __syncthreads();
        {   // split 256-length GEMV across both halves, 4 accumulators
            const float* qs = sxh + hf * 128;
            const float* wb = spw + hf * 16384 + e1;
            float a0 = 0.f, a1 = 0.f, a2 = 0.f, a3 = 0.f;
            #pragma unroll 8
            for (int q = 0; q < 128; q += 4) {
                a0 = fmaf(qs[q + 0], wb[(q + 0) * 128], a0);
                a1 = fmaf(qs[q + 1], wb[(q + 1) * 128], a1);
                a2 = fmaf(qs[q + 2], wb[(q + 2) * 128], a2);
                a3 = fmaf(qs[q + 3], wb[(q + 3) * 128], a3);
            }
            sred[tid] = (a0 + a1) + (a2 + a3);
        }
        __syncthreads();
        if (tid < 128) {
            float p = tanhf(rpb + sred[tid] + sred[128 + tid]);
            spred[tid] = p;
            g_rp[(slot1 * Bsz + b) * DWw + tid] = p;   // own-CTA ring
        }
        __syncthreads();
        if (warp < 4) {
            float s = NEGV;
            if (warp <= t) {
                const float* wp = &g_word[(((size_t)t * Bsz + b) * Lw + warp) * DWw];
                float acc = 0.0f;
                if (warp == 0) {
                    #pragma unroll
                    for (int e = 0; e < 128; e += 32) acc = fmaf(spred[lane + e], __ldcg(wp + lane + e), acc);
                } else {
                    const float* pp = &g_rp[(((t - 1 - warp) & 7) * Bsz + b) * DWw];
                    #pragma unroll
                    for (int e = 0; e < 128; e += 32) acc = fmaf(__ldcg(pp + lane + e), __ldcg(wp + lane + e), acc);
                }
                #pragma unroll
                for (int o = 16; o; o >>= 1) acc += __shfl_xor_sync(0xffffffffu, acc, o);
                if (lane == 0) s = acc + __ldcg(&g_su[(t * Bsz + b) * Lw + warp]);
            }
            if (lane == 0) ssc[warp] = s;
        }
        __syncthreads();
        if (tid == 0) {
            int best = 0; float bs = ssc[0];
            #pragma unroll
            for (int w = 1; w < 4; w++) if (ssc[w] > bs) { bs = ssc[w]; best = w; }
            __stcg(&g_best_i[b], best);
            out_sc[b * Tsz + t] = bs;
            out_wl[b * Tsz + t] = (float)(best + 1);
        }
        nbar++; gbar(bar, nbar * 16u);

        // ================= P2: LSTM for 16 rows x 16 units =================
        {
            const int best = __ldcg(&g_best_i[myrow]);
            const int hs = (t - 1 - best) & 7;

            float4 bq = *(const float4*)&sbias[lunit * 4];
            u64t aij[4], afo[4];
            aij[0] = pk2(bq.x, bq.y); afo[0] = pk2(bq.z, bq.w);
            aij[1] = aij[2] = aij[3] = 0ull;
            afo[1] = afo[2] = afo[3] = 0ull;

            const float4* wp = (const float4*)&g_word[(((size_t)t * Bsz + myrow) * Lw + best) * DWw];
            #pragma unroll 4
            for (int kq = 0; kq < 32; kq++) {
                float4 x4 = __ldcg(wp + kq);
                const ulonglong2* wr = (const ulonglong2*)&swl[kq * 256 + lunit * 4];
                ulonglong2 w0 = wr[0], w1 = wr[16], w2 = wr[32], w3 = wr[48];
                u64t xx;
                xx = dup2(x4.x); aij[0] = fma2(xx, w0.x, aij[0]); afo[0] = fma2(xx, w0.y, afo[0]);
                xx = dup2(x4.y); aij[1] = fma2(xx, w1.x, aij[1]); afo[1] = fma2(xx, w1.y, afo[1]);
                xx = dup2(x4.z); aij[2] = fma2(xx, w2.x, aij[2]); afo[2] = fma2(xx, w2.y, afo[2]);
                xx = dup2(x4.w); aij[3] = fma2(xx, w3.x, aij[3]); afo[3] = fma2(xx, w3.y, afo[3]);
            }
            const float4* hp = (const float4*)&g_rh[((size_t)(hs * Bsz) + myrow) * Hh];
            #pragma unroll 4
            for (int kq = 0; kq < 64; kq++) {
                float4 x4 = __ldcg(hp + kq);
                const ulonglong2* wr = (const ulonglong2*)&swl[(128 + kq * 4) * 64 + lunit * 4];
                ulonglong2 w0 = wr[0], w1 = wr[16], w2 = wr[32], w3 = wr[48];
                u64t xx;
                xx = dup2(x4.x); aij[0] = fma2(xx, w0.x, aij[0]); afo[0] = fma2(xx, w0.y, afo[0]);
                xx = dup2(x4.y); aij[1] = fma2(xx, w1.x, aij[1]); afo[1] = fma2(xx, w1.y, afo[1]);
                xx = dup2(x4.z); aij[2] = fma2(xx, w2.x, aij[2]); afo[2] = fma2(xx, w2.y, afo[2]);
                xx = dup2(x4.w); aij[3] = fma2(xx, w3.x, aij[3]); afo[3] = fma2(xx, w3.y, afo[3]);
            }
            u64t sij = add2(add2(aij[0], aij[1]), add2(aij[2], aij[3]));
            u64t sfo = add2(add2(afo[0], afo[1]), add2(afo[2], afo[3]));
            float2 fij = unpk(sij), ffo = unpk(sfo);
            float cp = __ldcg(&g_rc[((size_t)(hs * Bsz) + myrow) * Hh + unit]);
            float nc = cp * sigm(ffo.x) + sigm(fij.x) * tanhf(fij.y);
            float nh = tanhf(nc) * sigm(ffo.y);
            const int ws = t & 7;
            __stcg(&g_rc[((size_t)(ws * Bsz) + myrow) * Hh + unit], nc);
            __stcg(&g_rh[((size_t)(ws * Bsz) + myrow) * Hh + unit], nh);
        }
        nbar++; gbar(bar, nbar * 16u);
    }
}

// ---------------- launch ----------------
static const int PROJ_SMEM = (16384 + 16384 + 128 + 128 + 256 + 256) * 4;
static const int RUN_SMEM  = (32768 + 24576 + 256 + 128 + 256 + 64 + 8) * 4;

extern "C" void kernel_launch(void* const* d_in, const int* in_sizes, int n_in,
                              void* d_out, int out_size) {
    const int*   chars = (const int*)d_in[0];
    const float* emb   = (const float*)d_in[1];
    const float* rW    = (const float*)d_in[2];
    const float* rb    = (const float*)d_in[3];
    const float* cW    = (const float*)d_in[4];
    const float* cb    = (const float*)d_in[5];
    const float* lk    = (const float*)d_in[6];
    const float* lb    = (const float*)d_in[7];
    const float* pW    = (const float*)d_in[8];
    const float* pb    = (const float*)d_in[9];
    const float* U     = (const float*)d_in[10];
    const float* bos   = (const float*)d_in[11];

    cudaFuncSetAttribute(k_proj, cudaFuncAttributeMaxDynamicSharedMemorySize, PROJ_SMEM);
    cudaFuncSetAttribute(k_run,  cudaFuncAttributeMaxDynamicSharedMemorySize, RUN_SMEM);

    k_init<<<Bsz, 256>>>(lk, lb, pW, pb, bos);
    k_proj<<<dim3(37, 4), 256, PROJ_SMEM>>>(emb, rW, rb, cW, cb);
    k_word<<<dim3(Tsz, Bsz), 128>>>(chars, U);
    k_run<<<Bsz, 256, RUN_SMEM>>>(lk, lb, pW, pb, (float*)d_out);
}

// round 10
// speedup vs baseline: 1.6511x; 1.3917x over previous
#include <cuda_runtime.h>
#include <math.h>

#define Bsz 128
#define Tsz 256
#define Lw  4
#define DCc 128
#define DWw 128
#define Hh  256
#define Vv  6000
#define NEGV -1e30f

// ---------------- device global scratch (no allocations allowed) ----------------
__device__ float g_proj[Vv * Lw * DCc];                 // PROJ[ch][w][e]
__device__ float g_word[(size_t)Tsz * Bsz * Lw * DWw];  // word[t][b][w][e]
__device__ float g_su[Tsz * Bsz * Lw];                  // su[t][b][w]
__device__ float g_rh[8 * Bsz * Hh];                    // h ring [slot][b][u]
__device__ float g_rc[8 * Bsz * Hh];                    // c ring
__device__ float g_rp[8 * Bsz * DWw];                   // pred ring [slot][b][e]
__device__ int   g_best_i[Bsz];
__device__ unsigned g_arr[8 * 32];                      // per-group barrier counters (padded)

__device__ __forceinline__ float sigm(float x) { return 1.0f / (1.0f + expf(-x)); }

// ---------------- 16-CTA group barrier (monotonic epoch; reset by k_init) ----------
__device__ __forceinline__ void gbar(unsigned* ctr, unsigned target) {
    __syncthreads();
    if (threadIdx.x == 0) {
        __threadfence();
        atomicAdd(ctr, 1u);
        volatile unsigned* p = ctr;
        while (*p < target) { }
        __threadfence();
    }
    __syncthreads();
}

// ---------------- PROJ table (148 blocks = 1 wave, 2 chars/iter, 4 accumulators) ----
__global__ void k_proj(const float* __restrict__ emb,
                       const float* __restrict__ rW,
                       const float* __restrict__ rb,
                       const float* __restrict__ cW,
                       const float* __restrict__ cb) {
    extern __shared__ float sm[];
    float* srW = sm;               // 16384
    float* scW = srW + 16384;      // 16384
    float* srb = scW + 16384;      // 128
    float* scb = srb + 128;        // 128
    float* se  = scb + 128;        // 256
    float* sh  = se + 256;         // 256
    const int tid = threadIdx.x;   // 256 threads
    const int e = tid & 127, half = tid >> 7;
    const int w = blockIdx.y;

    for (int i = tid; i < 16384; i += 256) {
        srW[i] = rW[w * 16384 + i];
        scW[i] = cW[i];
    }
    if (tid < 128) { srb[tid] = rb[w * 128 + tid]; scb[tid] = cb[tid]; }
    __syncthreads();

    const int base = blockIdx.x * 163;
    for (int ci = 0; ci < 82; ci++) {
        const int ch = base + ci * 2 + half;
        const bool ok = (ci * 2 + half < 163) && (ch < Vv);
        se[half * 128 + e] = ok ? emb[ch * 128 + e] : 0.0f;
        __syncthreads();
        const float* seh = se + half * 128;
        float a0 = srb[e], a1 = 0.f, a2 = 0.f, a3 = 0.f;
        #pragma unroll 8
        for (int d = 0; d < 128; d += 4) {
            a0 = fmaf(seh[d + 0], srW[(d + 0) * 128 + e], a0);
            a1 = fmaf(seh[d + 1], srW[(d + 1) * 128 + e], a1);
            a2 = fmaf(seh[d + 2], srW[(d + 2) * 128 + e], a2);
            a3 = fmaf(seh[d + 3], srW[(d + 3) * 128 + e], a3);
        }
        float g = (a0 + a1) + (a2 + a3);
        sh[half * 128 + e] = sigm(g) * seh[e];
        __syncthreads();
        const float* shh = sh + half * 128;
        float p0 = scb[e], p1 = 0.f, p2 = 0.f, p3 = 0.f;
        #pragma unroll 8
        for (int d = 0; d < 128; d += 4) {
            p0 = fmaf(shh[d + 0], scW[(d + 0) * 128 + e], p0);
            p1 = fmaf(shh[d + 1], scW[(d + 1) * 128 + e], p1);
            p2 = fmaf(shh[d + 2], scW[(d + 2) * 128 + e], p2);
            p3 = fmaf(shh[d + 3], scW[(d + 3) * 128 + e], p3);
        }
        float p = (p0 + p1) + (p2 + p3);
        if (ok) g_proj[(ch * Lw + w) * DCc + e] = tanhf(p);
        __syncthreads();
    }
}

// ---------------- word + su tables ----------------
__global__ void k_word(const int* __restrict__ chars, const float* __restrict__ U) {
    const int t = blockIdx.x, b = blockIdx.y, tid = threadIdx.x; // 128 threads
    const int lane = tid & 31, wid = tid >> 5;
    __shared__ int ch[4];
    __shared__ float red[4];
    if (tid < 4) {
        int ti = t - tid;
        ch[tid] = (ti >= 0) ? chars[b * Tsz + ti] : 0;
    }
    __syncthreads();
    const float inv[4] = {1.0f, 0.5f, 1.0f / 3.0f, 0.25f};
    const float uw = U[tid];
    #pragma unroll
    for (int w = 0; w < 4; w++) {
        float acc = 0.0f;
        for (int c = 0; c <= w; c++) acc += g_proj[(ch[c] * Lw + w) * DCc + tid];
        acc *= inv[w];
        g_word[(((size_t)t * Bsz + b) * Lw + w) * DWw + tid] = acc;
        float v = acc * uw;
        #pragma unroll
        for (int o = 16; o; o >>= 1) v += __shfl_xor_sync(0xffffffffu, v, o);
        if (lane == 0) red[wid] = v;
        __syncthreads();
        if (tid == 0) g_su[(t * Bsz + b) * Lw + w] = red[0] + red[1] + red[2] + red[3];
        __syncthreads();
    }
}

// ---------------- init: c1,h1,pred0; prefill rings slots 4..7; reset barriers -------
__global__ void k_init(const float* __restrict__ lk, const float* __restrict__ lb,
                       const float* __restrict__ pW, const float* __restrict__ pb,
                       const float* __restrict__ bos) {
    __shared__ float sh1[256], sc1[256], sp0[128];
    const int u = threadIdx.x;  // 256 threads
    const int b = blockIdx.x;
    float zi = lb[u], zj = lb[256 + u], zo = lb[768 + u];
    for (int d = 0; d < 128; d++) {
        float x = bos[d];
        const float* row = lk + d * 1024;
        zi = fmaf(x, row[u], zi);
        zj = fmaf(x, row[256 + u], zj);
        zo = fmaf(x, row[768 + u], zo);
    }
    float nc = sigm(zi) * tanhf(zj);      // c0 = 0
    float nh = tanhf(nc) * sigm(zo);
    sc1[u] = nc; sh1[u] = nh;
    __syncthreads();
    if (u < 128) {
        float p = pb[u];
        for (int q = 0; q < 256; q++) p = fmaf(sh1[q], pW[q * 128 + u], p);
        sp0[u] = tanhf(p);
    }
    __syncthreads();
    for (int s = 4; s < 8; s++) {
        g_rc[(s * Bsz + b) * Hh + u] = sc1[u];
        g_rh[(s * Bsz + b) * Hh + u] = sh1[u];
        if (u < 128) g_rp[(s * Bsz + b) * DWw + u] = sp0[u];
    }
    if (b == 0 && u < 8) g_arr[u * 32] = 0u;
}

// ---------------- persistent sequential kernel ----------------
// CTA b: P1 (pred/score/argmax) for row b; P2 (LSTM) for rows bg*16..+15 x units
// ug*16..+15 (bg=b>>4, ug=b&15). P2 thread mapping: r=tid>>4 (row), uu=tid&15 (unit).
// Sync: two 16-CTA group barriers per step (all cross-CTA deps are intra-group).
__global__ void __launch_bounds__(256, 1) k_run(
    const float* __restrict__ lk, const float* __restrict__ lb,
    const float* __restrict__ pW, const float* __restrict__ pb,
    float* __restrict__ out) {
    extern __shared__ float sm[];
    float* spw   = sm;              // 32768: pred_W [u][e]
    float* swl   = spw + 32768;     // 24576: Wl[k][uu*4+g]
    float* sxh   = swl + 24576;     // 256
    float* spred = sxh + 256;       // 128
    float* sred  = spred + 128;     // 256
    float* sbias = sred + 256;      // 64
    float* ssc   = sbias + 64;      // 8

    const int tid = threadIdx.x;
    const int b = blockIdx.x;
    const int bg = b >> 4, ug = b & 15;
    const int lane = tid & 31, wid = tid >> 5;
    const int r = tid >> 4, uu = tid & 15;       // P2 roles
    const int bb = bg * 16 + r;
    const int unit = ug * 16 + uu;
    const int e1 = tid & 127, hf = tid >> 7;

    for (int i = tid; i < 32768; i += 256) spw[i] = pW[i];
    for (int i = tid; i < 24576; i += 256) {
        int k = i >> 6, m = i & 63, u2 = m >> 2, g = m & 3;
        swl[i] = lk[k * 1024 + g * 256 + ug * 16 + u2];
    }
    if (tid < 64) { int u2 = tid >> 2, g = tid & 3; sbias[tid] = lb[g * 256 + ug * 16 + u2]; }
    const float rpb = (tid < 128) ? pb[tid] : 0.0f;
    __syncthreads();

    unsigned nbar = 0;
    float* out_sc = out;
    float* out_wl = out + Bsz * Tsz;
    unsigned* bar = &g_arr[bg * 32];

    for (int t = 0; t < Tsz; t++) {
        // ================= P1: pred + score + argmax (row b) =================
        const int slot1 = (t + 7) & 7;  // (t-1) mod 8
        sxh[tid] = __ldcg(&g_rh[(slot1 * Bsz + b) * Hh + tid]);
        __syncthreads();
        {   // 256-length GEMV split across both halves, 4 accumulators
            const float* qs = sxh + hf * 128;
            const float* wb = spw + hf * 16384 + e1;
            float a0 = 0.f, a1 = 0.f, a2 = 0.f, a3 = 0.f;
            #pragma unroll 8
            for (int q = 0; q < 128; q += 4) {
                a0 = fmaf(qs[q + 0], wb[(q + 0) * 128], a0);
                a1 = fmaf(qs[q + 1], wb[(q + 1) * 128], a1);
                a2 = fmaf(qs[q + 2], wb[(q + 2) * 128], a2);
                a3 = fmaf(qs[q + 3], wb[(q + 3) * 128], a3);
            }
            sred[tid] = (a0 + a1) + (a2 + a3);
        }
        __syncthreads();
        if (tid < 128) {
            float p = tanhf(rpb + sred[tid] + sred[128 + tid]);
            spred[tid] = p;
            g_rp[(slot1 * Bsz + b) * DWw + tid] = p;   // own-CTA ring
        }
        __syncthreads();
        if (wid < 4) {
            float s = NEGV;
            if (wid <= t) {
                const float* wp = &g_word[(((size_t)t * Bsz + b) * Lw + wid) * DWw];
                float acc = 0.0f;
                if (wid == 0) {
                    for (int e = lane; e < 128; e += 32) acc = fmaf(spred[e], wp[e], acc);
                } else {
                    const float* pp = &g_rp[(((t - 1 - wid) & 7) * Bsz + b) * DWw];
                    for (int e = lane; e < 128; e += 32) acc = fmaf(pp[e], wp[e], acc);
                }
                #pragma unroll
                for (int o = 16; o; o >>= 1) acc += __shfl_xor_sync(0xffffffffu, acc, o);
                if (lane == 0) s = acc + g_su[(t * Bsz + b) * Lw + wid];
            }
            if (lane == 0) ssc[wid] = s;
        }
        __syncthreads();
        if (tid == 0) {
            int best = 0; float bs = ssc[0];
            #pragma unroll
            for (int w = 1; w < 4; w++) if (ssc[w] > bs) { bs = ssc[w]; best = w; }
            __stcg(&g_best_i[b], best);
            out_sc[b * Tsz + t] = bs;
            out_wl[b * Tsz + t] = (float)(best + 1);
        }
        nbar++; gbar(bar, nbar * 16u);

        // ================= P2: LSTM for 16 rows x 16 units =================
        {
            const int best = __ldcg(&g_best_i[bb]);
            const int hs = (t - 1 - best) & 7;
            float zi = sbias[uu * 4 + 0], zj = sbias[uu * 4 + 1];
            float zf = sbias[uu * 4 + 2], zo = sbias[uu * 4 + 3];
            const float4* xw = (const float4*)&g_word[(((size_t)t * Bsz + bb) * Lw + best) * DWw];
            #pragma unroll 4
            for (int kq = 0; kq < 32; kq++) {
                float4 x4 = __ldcg(xw + kq);
                const float* w0 = &swl[(kq * 4) * 64 + uu * 4];
                float4 a = *(const float4*)(w0);
                float4 c = *(const float4*)(w0 + 64);
                float4 d = *(const float4*)(w0 + 128);
                float4 e = *(const float4*)(w0 + 192);
                zi = fmaf(x4.x, a.x, zi); zj = fmaf(x4.x, a.y, zj); zf = fmaf(x4.x, a.z, zf); zo = fmaf(x4.x, a.w, zo);
                zi = fmaf(x4.y, c.x, zi); zj = fmaf(x4.y, c.y, zj); zf = fmaf(x4.y, c.z, zf); zo = fmaf(x4.y, c.w, zo);
                zi = fmaf(x4.z, d.x, zi); zj = fmaf(x4.z, d.y, zj); zf = fmaf(x4.z, d.z, zf); zo = fmaf(x4.z, d.w, zo);
                zi = fmaf(x4.w, e.x, zi); zj = fmaf(x4.w, e.y, zj); zf = fmaf(x4.w, e.z, zf); zo = fmaf(x4.w, e.w, zo);
            }
            const float4* hw = (const float4*)&g_rh[(hs * Bsz + bb) * Hh];
            #pragma unroll 4
            for (int kq = 0; kq < 64; kq++) {
                float4 x4 = __ldcg(hw + kq);
                const float* w0 = &swl[(128 + kq * 4) * 64 + uu * 4];
                float4 a = *(const float4*)(w0);
                float4 c = *(const float4*)(w0 + 64);
                float4 d = *(const float4*)(w0 + 128);
                float4 e = *(const float4*)(w0 + 192);
                zi = fmaf(x4.x, a.x, zi); zj = fmaf(x4.x, a.y, zj); zf = fmaf(x4.x, a.z, zf); zo = fmaf(x4.x, a.w, zo);
                zi = fmaf(x4.y, c.x, zi); zj = fmaf(x4.y, c.y, zj); zf = fmaf(x4.y, c.z, zf); zo = fmaf(x4.y, c.w, zo);
                zi = fmaf(x4.z, d.x, zi); zj = fmaf(x4.z, d.y, zj); zf = fmaf(x4.z, d.z, zf); zo = fmaf(x4.z, d.w, zo);
                zi = fmaf(x4.w, e.x, zi); zj = fmaf(x4.w, e.y, zj); zf = fmaf(x4.w, e.z, zf); zo = fmaf(x4.w, e.w, zo);
            }
            float cp = __ldcg(&g_rc[(hs * Bsz + bb) * Hh + unit]);
            float nc = cp * sigm(zf) + sigm(zi) * tanhf(zj);
            float nh = tanhf(nc) * sigm(zo);
            const int ws = t & 7;
            __stcg(&g_rc[(ws * Bsz + bb) * Hh + unit], nc);
            __stcg(&g_rh[(ws * Bsz + bb) * Hh + unit], nh);
        }
        nbar++; gbar(bar, nbar * 16u);
    }
}

// ---------------- launch ----------------
static const int PROJ_SMEM = (16384 + 16384 + 128 + 128 + 256 + 256) * 4;
static const int RUN_SMEM  = (32768 + 24576 + 256 + 128 + 256 + 64 + 8) * 4;

extern "C" void kernel_launch(void* const* d_in, const int* in_sizes, int n_in,
                              void* d_out, int out_size) {
    const int*   chars = (const int*)d_in[0];
    const float* emb   = (const float*)d_in[1];
    const float* rW    = (const float*)d_in[2];
    const float* rb    = (const float*)d_in[3];
    const float* cW    = (const float*)d_in[4];
    const float* cb    = (const float*)d_in[5];
    const float* lk    = (const float*)d_in[6];
    const float* lb    = (const float*)d_in[7];
    const float* pW    = (const float*)d_in[8];
    const float* pb    = (const float*)d_in[9];
    const float* U     = (const float*)d_in[10];
    const float* bos   = (const float*)d_in[11];

    cudaFuncSetAttribute(k_proj, cudaFuncAttributeMaxDynamicSharedMemorySize, PROJ_SMEM);
    cudaFuncSetAttribute(k_run,  cudaFuncAttributeMaxDynamicSharedMemorySize, RUN_SMEM);

    k_init<<<Bsz, 256>>>(lk, lb, pW, pb, bos);
    k_proj<<<dim3(37, 4), 256, PROJ_SMEM>>>(emb, rW, rb, cW, cb);
    k_word<<<dim3(Tsz, Bsz), 128>>>(chars, U);
    k_run<<<Bsz, 256, RUN_SMEM>>>(lk, lb, pW, pb, (float*)d_out);
}